// round 6
// baseline (speedup 1.0000x reference)
#include <cuda_runtime.h>
#include <cstdint>

#define Tlen 1024
#define NCTA 128
#define NTHR 512

typedef unsigned long long ull;

// ---- static shared layout ----
struct __align__(16) Smem {
    ull   mb_h1[3];        // per-buffer mbarriers for h1 arrivals (count=4)
    ull   mb_h2[3];        // per-buffer mbarriers for h2 arrivals (count=4)
    float pad[4];          // keep hc 16B-aligned
    float hc[3][4][196];   // [buf][batch][h1(0..127) ++ h2(128..191)]
    float a1[512];         // L1 gate partials [g*128 + dl*4 + ks]
    float a2[256];         // L2 gate partials [g*64 + dl*4 + ks]
    float xs[4][1024];     // staged x
};
__shared__ Smem sm;

__device__ __forceinline__ float tanha(float x) {
    float y; asm("tanh.approx.f32 %0, %1;" : "=f"(y) : "f"(x)); return y;
}
__device__ __forceinline__ float sigm(float v) { return fmaf(tanha(0.5f * v), 0.5f, 0.5f); }

__device__ __forceinline__ uint32_t s2u(const void* p) {
    uint32_t a;
    asm("{ .reg .u64 t; cvta.to.shared.u64 t, %1; cvt.u32.u64 %0, t; }" : "=r"(a) : "l"(p));
    return a;
}
__device__ __forceinline__ uint32_t mapa_r(uint32_t saddr, int rank) {
    uint32_t r;
    asm volatile("mapa.shared::cluster.u32 %0, %1, %2;" : "=r"(r) : "r"(saddr), "r"(rank));
    return r;
}
__device__ __forceinline__ void st_cl(uint32_t addr, float v) {
    asm volatile("st.shared::cluster.f32 [%0], %1;" :: "r"(addr), "f"(v) : "memory");
}
__device__ __forceinline__ void marr(uint32_t addr) {   // remote (cluster-mapped) arrive
    asm volatile("mbarrier.arrive.shared::cluster.b64 _, [%0];" :: "r"(addr) : "memory");
}
__device__ __forceinline__ void fence_cluster() {
    asm volatile("fence.acq_rel.cluster;" ::: "memory");
}
__device__ __forceinline__ void mwait(uint32_t mbar, uint32_t parity) {
    asm volatile(
        "{\n\t.reg .pred P1;\n\t"
        "WAIT_LOOP_%=:\n\t"
        "mbarrier.try_wait.parity.acquire.cta.shared::cta.b64 P1, [%0], %1, 0x989680;\n\t"
        "@P1 bra.uni WAIT_DONE_%=;\n\t"
        "bra.uni WAIT_LOOP_%=;\n\t"
        "WAIT_DONE_%=:\n\t}"
        :: "r"(mbar), "r"(parity) : "memory");
}
__device__ __forceinline__ void csync() {
    asm volatile("barrier.cluster.arrive.aligned;" ::: "memory");
    asm volatile("barrier.cluster.wait.aligned;" ::: "memory");
}
__device__ __forceinline__ void ffma2(ull& acc, ull a, ull b) {
    asm("fma.rn.f32x2 %0, %1, %2, %0;" : "+l"(acc) : "l"(a), "l"(b));
}
__device__ __forceinline__ float2 u2f2(ull u) {
    float2 f;
    asm("mov.b64 {%0, %1}, %2;" : "=f"(f.x), "=f"(f.y) : "l"(u));
    return f;
}
__device__ __forceinline__ ull pk(float lo, float hi) {
    ull r;
    asm("mov.b64 %0, {%1, %2};" : "=l"(r) : "f"(lo), "f"(hi));
    return r;
}

#define HC_BUF_BYTES (4 * 196 * 4)

__global__ void __launch_bounds__(NTHR, 1) __cluster_dims__(4, 1, 1)
lstm_cluster_kernel(
    const float* __restrict__ x,
    const float* __restrict__ w_ih1,  // [512][1]
    const float* __restrict__ w_hh1,  // [512][128]
    const float* __restrict__ b_ih1,
    const float* __restrict__ b_hh1,
    const float* __restrict__ w_ih2,  // [256][128]
    const float* __restrict__ w_hh2,  // [256][64]
    const float* __restrict__ b_ih2,
    const float* __restrict__ b_hh2,
    float* __restrict__ out)          // [128][64]
{
    const int tid = threadIdx.x;
    const int q   = blockIdx.x & 3;
    const int cid = blockIdx.x >> 2;

    // ---------------- compute roles (identical to R5) ----------------
    const int ks1 = tid & 3;
    const int dl1 = (tid >> 2) & 31;
    const int g1  = tid >> 7;
    const int ks2 = tid & 7;
    const int dl2 = (tid >> 3) & 15;
    const int g2  = tid >> 7;

    // ---------------- weights -> registers (striped, as R5) ----------------
    const int row1w = g1 * 128 + 32 * q + dl1;
    ulonglong2 w1u[8];
    {
        const float* wr = w_hh1 + row1w * 128 + ks1 * 4;
#pragma unroll
        for (int kk = 0; kk < 8; kk++) {
            float4 f = *reinterpret_cast<const float4*>(wr + kk * 16);
            w1u[kk].x = pk(f.x, f.y);
            w1u[kk].y = pk(f.z, f.w);
        }
    }
    const int row2w = g2 * 64 + 16 * q + dl2;
    ulonglong2 w2u[6];
    {
#pragma unroll
        for (int kk = 0; kk < 6; kk++) {
            int k0 = ks2 * 4 + kk * 32;
            float f[4];
#pragma unroll
            for (int e = 0; e < 4; e++) {
                int k = k0 + e;
                f[e] = (k < 128) ? w_ih2[row2w * 128 + k] : w_hh2[row2w * 64 + (k - 128)];
            }
            w2u[kk].x = pk(f[0], f[1]);
            w2u[kk].y = pk(f[2], f[3]);
        }
    }

    // combiner constants: L1 -> tid<128, L2 -> tid in [128,192)
    float wihc[4], b1c[4];
    if (tid < 128) {
        int d = tid >> 2;
#pragma unroll
        for (int g = 0; g < 4; g++) {
            int row = g * 128 + 32 * q + d;
            wihc[g] = w_ih1[row];
            b1c[g]  = b_ih1[row] + b_hh1[row];
        }
    }
    float b2c[4];
    if (tid >= 128 && tid < 192) {
        int d2 = 16 * q + ((tid - 128) >> 2);
#pragma unroll
        for (int g = 0; g < 4; g++) b2c[g] = b_ih2[g * 64 + d2] + b_hh2[g * 64 + d2];
    }

    // ---------------- init smem ----------------
    for (int idx = tid; idx < 4 * 1024; idx += NTHR) {
        int b = idx >> 10, t = idx & 1023;
        sm.xs[b][t] = x[(4 * cid + b) * 1024 + t];
    }
    for (int idx = tid; idx < 3 * 4 * 196; idx += NTHR)
        (&sm.hc[0][0][0])[idx] = 0.0f;
    if (tid == 0) {
#pragma unroll
        for (int j = 0; j < 3; j++) {
            uint32_t a1m = s2u(&sm.mb_h1[j]);
            uint32_t a2m = s2u(&sm.mb_h2[j]);
            asm volatile("mbarrier.init.shared.b64 [%0], 4;" :: "r"(a1m) : "memory");
            asm volatile("mbarrier.init.shared.b64 [%0], 4;" :: "r"(a2m) : "memory");
        }
    }

    // ---------------- cluster address constants ----------------
    const uint32_t base0 = s2u(&sm);
    const uint32_t m0    = mapa_r(base0, 0);
    const uint32_t dd1   = mapa_r(base0, 1) - m0;
    const uint32_t dd2   = mapa_r(base0, 2) - m0;
    const uint32_t dd3   = mapa_r(base0, 3) - m0;
    const uint32_t HCO   = s2u(&sm.hc[0][0][0]) - base0;
    const uint32_t MB1O  = s2u(&sm.mb_h1[0]) - base0;
    const uint32_t MB2O  = s2u(&sm.mb_h2[0]) - base0;
    // per-lane fixed store offsets (bytes from hc base within a buffer)
    const uint32_t loff1 = ((tid & 3) * 196 + 32 * q + (tid >> 2)) * 4;                 // tid<128
    const uint32_t loff2 = (((tid - 128) & 3) * 196 + 128 + 16 * q + ((tid - 128) >> 2)) * 4;

    csync();  // mbars + zeroed smem visible cluster-wide

    float c1 = 0.0f, c2 = 0.0f;

    for (int i = 0; i <= Tlen; i++) {
        const int bufW = i % 3;
        int bufR;
        if (i >= 1) {
            const int im1 = i - 1;
            bufR = im1 % 3;
            const uint32_t ph = (uint32_t)((im1 / 3) & 1);
            mwait(base0 + MB1O + bufR * 8, ph);
            mwait(base0 + MB2O + bufR * 8, ph);
            fence_cluster();   // acquire remote stores
        } else {
            bufR = 2;          // zeroed buffer
        }

        // ---- P1: L2 partials (for L2 step i-1) ----
        if (i >= 1) {
            float s[4];
#pragma unroll
            for (int b = 0; b < 4; b++) {
                const ulonglong2* hp =
                    reinterpret_cast<const ulonglong2*>(&sm.hc[bufR][b][0]);
                ull a0 = 0ull, a1 = 0ull;
#pragma unroll
                for (int kk = 0; kk < 6; kk++) {
                    ulonglong2 h = hp[ks2 + 8 * kk];
                    ffma2(a0, h.x, w2u[kk].x);
                    ffma2(a1, h.y, w2u[kk].y);
                }
                float2 f0 = u2f2(a0), f1 = u2f2(a1);
                float v = (f0.x + f0.y) + (f1.x + f1.y);
                v += __shfl_xor_sync(0xffffffffu, v, 1);
                v += __shfl_xor_sync(0xffffffffu, v, 2);
                v += __shfl_xor_sync(0xffffffffu, v, 4);
                s[b] = v;
            }
            if (ks2 < 4) {
                float v = (ks2 == 0) ? s[0] : (ks2 == 1) ? s[1] : (ks2 == 2) ? s[2] : s[3];
                sm.a2[g2 * 64 + dl2 * 4 + ks2] = v;
            }
        }
        __syncthreads();

        // ---- P2: L1 partials (step i) ----
        if (i < Tlen) {
            float s[4];
#pragma unroll
            for (int b = 0; b < 4; b++) {
                const ulonglong2* hp =
                    reinterpret_cast<const ulonglong2*>(&sm.hc[bufR][b][0]);
                ull a0 = 0ull, a1 = 0ull;
#pragma unroll
                for (int kk = 0; kk < 8; kk++) {
                    ulonglong2 h = hp[ks1 + 4 * kk];
                    ffma2(a0, h.x, w1u[kk].x);
                    ffma2(a1, h.y, w1u[kk].y);
                }
                float2 f0 = u2f2(a0), f1 = u2f2(a1);
                float v = (f0.x + f0.y) + (f1.x + f1.y);
                v += __shfl_xor_sync(0xffffffffu, v, 1);
                v += __shfl_xor_sync(0xffffffffu, v, 2);
                s[b] = v;
            }
            float v = (ks1 == 0) ? s[0] : (ks1 == 1) ? s[1] : (ks1 == 2) ? s[2] : s[3];
            sm.a1[g1 * 128 + dl1 * 4 + ks1] = v;
        }
        __syncthreads();

        // ---- P3a: L1 combine + scatter (lanes 0..127) ----
        if (i < Tlen && tid < 128) {
            int b = tid & 3;
            float xv = sm.xs[b][i];
            float ai = fmaf(xv, wihc[0], sm.a1[tid]       + b1c[0]);
            float af = fmaf(xv, wihc[1], sm.a1[128 + tid] + b1c[1]);
            float ag = fmaf(xv, wihc[2], sm.a1[256 + tid] + b1c[2]);
            float ao = fmaf(xv, wihc[3], sm.a1[384 + tid] + b1c[3]);
            c1 = sigm(af) * c1 + sigm(ai) * tanha(ag);
            float h = sigm(ao) * tanha(c1);
            uint32_t a = m0 + HCO + bufW * HC_BUF_BYTES + loff1;
            st_cl(a, h); st_cl(a + dd1, h); st_cl(a + dd2, h); st_cl(a + dd3, h);
            asm volatile("bar.sync 1, 128;" ::: "memory");
            if (tid == 0) {
                fence_cluster();
                uint32_t am = m0 + MB1O + bufW * 8;
                marr(am); marr(am + dd1); marr(am + dd2); marr(am + dd3);
            }
        }

        // ---- P3b: L2 combine + scatter / output (lanes 128..191) ----
        if (tid >= 128 && tid < 192) {
            int l = tid - 128;
            float h;
            if (i == 0) {
                h = 0.0f;   // h2 initial state
            } else {
                float ai = sm.a2[l]       + b2c[0];
                float af = sm.a2[64 + l]  + b2c[1];
                float ag = sm.a2[128 + l] + b2c[2];
                float ao = sm.a2[192 + l] + b2c[3];
                c2 = sigm(af) * c2 + sigm(ai) * tanha(ag);
                h = sigm(ao) * tanha(c2);
            }
            if (i == Tlen) {
                int b = l & 3, d = l >> 2;
                out[(4 * cid + b) * 64 + 16 * q + d] = h;
            } else {
                uint32_t a = m0 + HCO + bufW * HC_BUF_BYTES + loff2;
                st_cl(a, h); st_cl(a + dd1, h); st_cl(a + dd2, h); st_cl(a + dd3, h);
                asm volatile("bar.sync 2, 64;" ::: "memory");
                if (l == 0) {
                    fence_cluster();
                    uint32_t am = m0 + MB2O + bufW * 8;
                    marr(am); marr(am + dd1); marr(am + dd2); marr(am + dd3);
                }
            }
        }
    }

    csync();  // cluster lifetime: no early exit while peers may touch our smem
}

extern "C" void kernel_launch(void* const* d_in, const int* in_sizes, int n_in,
                              void* d_out, int out_size) {
    const float* x     = (const float*)d_in[0];
    const float* w_ih1 = (const float*)d_in[1];
    const float* w_hh1 = (const float*)d_in[2];
    const float* b_ih1 = (const float*)d_in[3];
    const float* b_hh1 = (const float*)d_in[4];
    const float* w_ih2 = (const float*)d_in[5];
    const float* w_hh2 = (const float*)d_in[6];
    const float* b_ih2 = (const float*)d_in[7];
    const float* b_hh2 = (const float*)d_in[8];
    float* out = (float*)d_out;

    lstm_cluster_kernel<<<NCTA, NTHR>>>(
        x, w_ih1, w_hh1, b_ih1, b_hh1, w_ih2, w_hh2, b_ih2, b_hh2, out);
    (void)in_sizes; (void)n_in; (void)out_size;
}

// round 7
// speedup vs baseline: 1.7172x; 1.7172x over previous
#include <cuda_runtime.h>
#include <cstdint>

#define Tlen 1024
#define NCTA 128
#define NTHR 512

typedef unsigned long long ull;

struct __align__(16) Smem {
    ull   mb[3];           // one mbarrier per hc buffer (count = 4 source CTAs)
    ull   pad_;            // 16B align hc
    float hc[3][4][196];   // [buf][batch][h1(0..127) ++ h2(128..191)]
    float xs[4][1024];     // staged x
};
__shared__ Smem sm;

__device__ __forceinline__ float tanha(float x) {
    float y; asm("tanh.approx.f32 %0, %1;" : "=f"(y) : "f"(x)); return y;
}
__device__ __forceinline__ float sigm(float v) { return fmaf(tanha(0.5f * v), 0.5f, 0.5f); }

__device__ __forceinline__ uint32_t s2u(const void* p) {
    uint32_t a;
    asm("{ .reg .u64 t; cvta.to.shared.u64 t, %1; cvt.u32.u64 %0, t; }" : "=r"(a) : "l"(p));
    return a;
}
__device__ __forceinline__ uint32_t mapa_r(uint32_t saddr, int rank) {
    uint32_t r;
    asm volatile("mapa.shared::cluster.u32 %0, %1, %2;" : "=r"(r) : "r"(saddr), "r"(rank));
    return r;
}
__device__ __forceinline__ void st_cl(uint32_t addr, float v) {
    asm volatile("st.shared::cluster.f32 [%0], %1;" :: "r"(addr), "f"(v) : "memory");
}
__device__ __forceinline__ void marr(uint32_t addr) {
    asm volatile("mbarrier.arrive.shared::cluster.b64 _, [%0];" :: "r"(addr) : "memory");
}
__device__ __forceinline__ void fence_cluster() {
    asm volatile("fence.acq_rel.cluster;" ::: "memory");
}
__device__ __forceinline__ void mwait(uint32_t mbar, uint32_t parity) {
    asm volatile(
        "{\n\t.reg .pred P1;\n\t"
        "WAIT_LOOP_%=:\n\t"
        "mbarrier.try_wait.parity.acquire.cta.shared::cta.b64 P1, [%0], %1, 0x989680;\n\t"
        "@P1 bra.uni WAIT_DONE_%=;\n\t"
        "bra.uni WAIT_LOOP_%=;\n\t"
        "WAIT_DONE_%=:\n\t}"
        :: "r"(mbar), "r"(parity) : "memory");
}
__device__ __forceinline__ void csync() {
    asm volatile("barrier.cluster.arrive.aligned;" ::: "memory");
    asm volatile("barrier.cluster.wait.aligned;" ::: "memory");
}
__device__ __forceinline__ void ffma2(ull& acc, ull a, ull b) {
    asm("fma.rn.f32x2 %0, %1, %2, %0;" : "+l"(acc) : "l"(a), "l"(b));
}
__device__ __forceinline__ float2 u2f2(ull u) {
    float2 f;
    asm("mov.b64 {%0, %1}, %2;" : "=f"(f.x), "=f"(f.y) : "l"(u));
    return f;
}
__device__ __forceinline__ ull pk(float lo, float hi) {
    ull r;
    asm("mov.b64 %0, {%1, %2};" : "=l"(r) : "f"(lo), "f"(hi));
    return r;
}

// 4x4 gate<->batch transpose across lane bits [0:1]. On entry lane G holds
// s[b] = M[G][b]; on exit s[j] = M[j][G].
__device__ __forceinline__ void transpose4(float s[4], int G) {
    const unsigned FULL = 0xffffffffu;
    int g0 = G & 1, g1 = (G >> 1) & 1;
    float x0 = g0 ? s[0] : s[1];
    float x1 = g0 ? s[2] : s[3];
    float y0 = __shfl_xor_sync(FULL, x0, 1);
    float y1 = __shfl_xor_sync(FULL, x1, 1);
    if (g0) { s[0] = y0; s[2] = y1; } else { s[1] = y0; s[3] = y1; }
    x0 = g1 ? s[0] : s[2];
    x1 = g1 ? s[1] : s[3];
    y0 = __shfl_xor_sync(FULL, x0, 2);
    y1 = __shfl_xor_sync(FULL, x1, 2);
    if (g1) { s[0] = y0; s[1] = y1; } else { s[2] = y0; s[3] = y1; }
}

#define HC_BUF_BYTES (4 * 196 * 4)

__global__ void __launch_bounds__(NTHR, 1) __cluster_dims__(4, 1, 1)
lstm_cluster_kernel(
    const float* __restrict__ x,
    const float* __restrict__ w_ih1,  // [512][1]
    const float* __restrict__ w_hh1,  // [512][128]
    const float* __restrict__ b_ih1,
    const float* __restrict__ b_hh1,
    const float* __restrict__ w_ih2,  // [256][128]
    const float* __restrict__ w_hh2,  // [256][64]
    const float* __restrict__ b_ih2,
    const float* __restrict__ b_hh2,
    float* __restrict__ out)          // [128][64]
{
    const int tid  = threadIdx.x;
    const int lane = tid & 31;
    const int wrp  = tid >> 5;        // 16 warps
    const int q    = blockIdx.x & 3;
    const int cid  = blockIdx.x >> 2;

    // ---- L1 lane roles: lane = g(2b) | ks1(2b)<<2 | dlb<<4 ; warp -> dl pair ----
    const int g    = lane & 3;
    const int ks1  = (lane >> 2) & 3;
    const int dlb  = (lane >> 4) & 1;
    const int dl   = wrp * 2 + dlb;   // 0..31
    // ---- L2 lane roles: lane = g(2b) | ks2(3b)<<2 ; warp -> dl2 ----
    const int ks2  = lane >> 2;       // 0..7
    const int dl2  = wrp;             // 0..15

    // ---------------- weights -> registers (striped) ----------------
    const int row1 = g * 128 + 32 * q + dl;
    ulonglong2 w1u[8];
    {
        const float* wr = w_hh1 + row1 * 128 + ks1 * 4;
#pragma unroll
        for (int kk = 0; kk < 8; kk++) {
            float4 f = *reinterpret_cast<const float4*>(wr + kk * 16);
            w1u[kk].x = pk(f.x, f.y);
            w1u[kk].y = pk(f.z, f.w);
        }
    }
    const int row2 = g * 64 + 16 * q + dl2;
    ulonglong2 w2u[6];
    {
#pragma unroll
        for (int kk = 0; kk < 6; kk++) {
            int k0 = ks2 * 4 + kk * 32;
            float f[4];
#pragma unroll
            for (int e = 0; e < 4; e++) {
                int k = k0 + e;
                f[e] = (k < 128) ? w_ih2[row2 * 128 + k] : w_hh2[row2 * 64 + (k - 128)];
            }
            w2u[kk].x = pk(f[0], f[1]);
            w2u[kk].y = pk(f[2], f[3]);
        }
    }

    // per-lane gate constants (all 4 gates; used after transpose)
    float wihc[4], b1c[4], b2c[4];
#pragma unroll
    for (int j = 0; j < 4; j++) {
        int r1 = j * 128 + 32 * q + dl;
        wihc[j] = w_ih1[r1];
        b1c[j]  = b_ih1[r1] + b_hh1[r1];
        int r2 = j * 64 + 16 * q + dl2;
        b2c[j]  = b_ih2[r2] + b_hh2[r2];
    }

    // ---------------- init smem ----------------
    for (int idx = tid; idx < 4 * 1024; idx += NTHR) {
        int b = idx >> 10, t = idx & 1023;
        sm.xs[b][t] = x[(4 * cid + b) * 1024 + t];
    }
    for (int idx = tid; idx < 3 * 4 * 196; idx += NTHR)
        (&sm.hc[0][0][0])[idx] = 0.0f;
    if (tid == 0) {
#pragma unroll
        for (int j = 0; j < 3; j++) {
            uint32_t a = s2u(&sm.mb[j]);
            asm volatile("mbarrier.init.shared.b64 [%0], 4;" :: "r"(a) : "memory");
        }
    }

    // ---------------- cluster address constants ----------------
    const uint32_t base0 = s2u(&sm);
    const uint32_t m0    = mapa_r(base0, 0);
    uint32_t dd[4];
    dd[0] = 0;
    dd[1] = mapa_r(base0, 1) - m0;
    dd[2] = mapa_r(base0, 2) - m0;
    dd[3] = mapa_r(base0, 3) - m0;
    const uint32_t HCO = s2u(&sm.hc[0][0][0]) - base0;
    const uint32_t MBO = s2u(&sm.mb[0]) - base0;
    // destination rank for this lane's replica store
    const uint32_t rk1 = m0 + dd[ks1];
    const uint32_t rk2 = m0 + dd[ks2 & 3];

    csync();  // mbars + zeroed smem visible cluster-wide

    float c1 = 0.0f, c2 = 0.0f;
    const unsigned FULL = 0xffffffffu;

    for (int i = 0; i <= Tlen; i++) {
        const int bufW = i % 3;
        int bufR = 2;                 // zeroed buffer for i==0
        if (i >= 1) {
            const int im1 = i - 1;
            bufR = im1 % 3;
            mwait(base0 + MBO + bufR * 8, (uint32_t)((im1 / 3) & 1));
        }

        // ======== L1 (step i): dot + ks-allreduce + transpose + cell + store ========
        if (i < Tlen) {
            float s[4];
#pragma unroll
            for (int b = 0; b < 4; b++) {
                const ulonglong2* hp =
                    reinterpret_cast<const ulonglong2*>(&sm.hc[bufR][b][0]);
                ull a0 = 0ull, a1 = 0ull;
#pragma unroll
                for (int kk = 0; kk < 8; kk++) {
                    ulonglong2 h = hp[ks1 + 4 * kk];
                    ffma2(a0, h.x, w1u[kk].x);
                    ffma2(a1, h.y, w1u[kk].y);
                }
                float2 f0 = u2f2(a0), f1 = u2f2(a1);
                s[b] = (f0.x + f0.y) + (f1.x + f1.y);
            }
            // allreduce over ks1 (lane bits 2,3)
#pragma unroll
            for (int b = 0; b < 4; b++) {
                s[b] += __shfl_xor_sync(FULL, s[b], 4);
                s[b] += __shfl_xor_sync(FULL, s[b], 8);
            }
            transpose4(s, g);         // now s[j] = gate-j preact for batch beta=g
            const int beta = g;
            float xv = sm.xs[beta][i];
            float ai = fmaf(xv, wihc[0], s[0] + b1c[0]);
            float af = fmaf(xv, wihc[1], s[1] + b1c[1]);
            float ag = fmaf(xv, wihc[2], s[2] + b1c[2]);
            float ao = fmaf(xv, wihc[3], s[3] + b1c[3]);
            c1 = sigm(af) * c1 + sigm(ai) * tanha(ag);
            float h = sigm(ao) * tanha(c1);
            st_cl(rk1 + HCO + bufW * HC_BUF_BYTES + (beta * 196 + 32 * q + dl) * 4, h);
        }

        // ======== L2 (step i-1): dot + ks2-allreduce + transpose + cell + store ========
        {
            float h2v = 0.0f;
            if (i >= 1) {
                float s[4];
#pragma unroll
                for (int b = 0; b < 4; b++) {
                    const ulonglong2* hp =
                        reinterpret_cast<const ulonglong2*>(&sm.hc[bufR][b][0]);
                    ull a0 = 0ull, a1 = 0ull;
#pragma unroll
                    for (int kk = 0; kk < 6; kk++) {
                        ulonglong2 h = hp[ks2 + 8 * kk];
                        ffma2(a0, h.x, w2u[kk].x);
                        ffma2(a1, h.y, w2u[kk].y);
                    }
                    float2 f0 = u2f2(a0), f1 = u2f2(a1);
                    s[b] = (f0.x + f0.y) + (f1.x + f1.y);
                }
#pragma unroll
                for (int b = 0; b < 4; b++) {
                    s[b] += __shfl_xor_sync(FULL, s[b], 4);
                    s[b] += __shfl_xor_sync(FULL, s[b], 8);
                    s[b] += __shfl_xor_sync(FULL, s[b], 16);
                }
                transpose4(s, g);
                float ai = s[0] + b2c[0];
                float af = s[1] + b2c[1];
                float ag = s[2] + b2c[2];
                float ao = s[3] + b2c[3];
                c2 = sigm(af) * c2 + sigm(ai) * tanha(ag);
                h2v = sigm(ao) * tanha(c2);
            }
            const int beta = g;
            if (i == Tlen) {
                if (ks2 == 0)
                    out[(4 * cid + beta) * 64 + 16 * q + dl2] = h2v;
            } else if (ks2 < 4) {
                st_cl(rk2 + HCO + bufW * HC_BUF_BYTES + (beta * 196 + 128 + 16 * q + dl2) * 4,
                      h2v);
            }
        }

        // ======== publish step i's buffer ========
        if (i < Tlen) {
            __syncthreads();
            if (tid == 0) {
                fence_cluster();
                uint32_t am = m0 + MBO + bufW * 8;
                marr(am); marr(am + dd[1]); marr(am + dd[2]); marr(am + dd[3]);
            }
        }
    }

    csync();  // keep smem alive for peers
}

extern "C" void kernel_launch(void* const* d_in, const int* in_sizes, int n_in,
                              void* d_out, int out_size) {
    const float* x     = (const float*)d_in[0];
    const float* w_ih1 = (const float*)d_in[1];
    const float* w_hh1 = (const float*)d_in[2];
    const float* b_ih1 = (const float*)d_in[3];
    const float* b_hh1 = (const float*)d_in[4];
    const float* w_ih2 = (const float*)d_in[5];
    const float* w_hh2 = (const float*)d_in[6];
    const float* b_ih2 = (const float*)d_in[7];
    const float* b_hh2 = (const float*)d_in[8];
    float* out = (float*)d_out;

    lstm_cluster_kernel<<<NCTA, NTHR>>>(
        x, w_ih1, w_hh1, b_ih1, b_hh1, w_ih2, w_hh2, b_ih2, b_hh2, out);
    (void)in_sizes; (void)n_in; (void)out_size;
}

// round 8
// speedup vs baseline: 1.9800x; 1.1531x over previous
#include <cuda_runtime.h>
#include <cstdint>

#define Tlen 1024
#define NCTA 128
#define NTHR 256

typedef unsigned long long ull;

struct __align__(16) Smem {
    ull   mb[3];           // one mbarrier per hc buffer (count = 4 source CTAs)
    ull   pad_;
    float hc[3][4][196];   // [buf][batch][h1(0..127) ++ h2(128..191)]
    float xs[1024][4];     // staged x, interleaved [t][b] (conflict-free gate read)
};
__shared__ Smem sm;

__device__ __forceinline__ float tanha(float x) {
    float y; asm("tanh.approx.f32 %0, %1;" : "=f"(y) : "f"(x)); return y;
}
__device__ __forceinline__ float sigm(float v) { return fmaf(tanha(0.5f * v), 0.5f, 0.5f); }

__device__ __forceinline__ uint32_t s2u(const void* p) {
    uint32_t a;
    asm("{ .reg .u64 t; cvta.to.shared.u64 t, %1; cvt.u32.u64 %0, t; }" : "=r"(a) : "l"(p));
    return a;
}
__device__ __forceinline__ uint32_t mapa_r(uint32_t saddr, int rank) {
    uint32_t r;
    asm volatile("mapa.shared::cluster.u32 %0, %1, %2;" : "=r"(r) : "r"(saddr), "r"(rank));
    return r;
}
__device__ __forceinline__ void st_cl(uint32_t addr, float v) {
    asm volatile("st.shared::cluster.f32 [%0], %1;" :: "r"(addr), "f"(v) : "memory");
}
__device__ __forceinline__ void marr(uint32_t addr) {
    asm volatile("mbarrier.arrive.shared::cluster.b64 _, [%0];" :: "r"(addr) : "memory");
}
__device__ __forceinline__ void fence_cluster() {
    asm volatile("fence.acq_rel.cluster;" ::: "memory");
}
__device__ __forceinline__ void mwait(uint32_t mbar, uint32_t parity) {
    asm volatile(
        "{\n\t.reg .pred P1;\n\t"
        "WAIT_LOOP_%=:\n\t"
        "mbarrier.try_wait.parity.acquire.cta.shared::cta.b64 P1, [%0], %1, 0x989680;\n\t"
        "@P1 bra.uni WAIT_DONE_%=;\n\t"
        "bra.uni WAIT_LOOP_%=;\n\t"
        "WAIT_DONE_%=:\n\t}"
        :: "r"(mbar), "r"(parity) : "memory");
}
__device__ __forceinline__ void csync() {
    asm volatile("barrier.cluster.arrive.aligned;" ::: "memory");
    asm volatile("barrier.cluster.wait.aligned;" ::: "memory");
}
__device__ __forceinline__ void ffma2(ull& acc, ull a, ull b) {
    asm("fma.rn.f32x2 %0, %1, %2, %0;" : "+l"(acc) : "l"(a), "l"(b));
}
__device__ __forceinline__ float2 u2f2(ull u) {
    float2 f;
    asm("mov.b64 {%0, %1}, %2;" : "=f"(f.x), "=f"(f.y) : "l"(u));
    return f;
}
__device__ __forceinline__ ull pk(float lo, float hi) {
    ull r;
    asm("mov.b64 %0, {%1, %2};" : "=l"(r) : "f"(lo), "f"(hi));
    return r;
}

// 4x4 gate<->batch transpose across lane bits [0:1]; lane G: in s[b]=M[G][b],
// out s[j]=M[j][G].
__device__ __forceinline__ void transpose4(float s[4], int G) {
    const unsigned FULL = 0xffffffffu;
    int g0 = G & 1, g1 = (G >> 1) & 1;
    float x0 = g0 ? s[0] : s[1];
    float x1 = g0 ? s[2] : s[3];
    float y0 = __shfl_xor_sync(FULL, x0, 1);
    float y1 = __shfl_xor_sync(FULL, x1, 1);
    if (g0) { s[0] = y0; s[2] = y1; } else { s[1] = y0; s[3] = y1; }
    x0 = g1 ? s[0] : s[2];
    x1 = g1 ? s[1] : s[3];
    y0 = __shfl_xor_sync(FULL, x0, 2);
    y1 = __shfl_xor_sync(FULL, x1, 2);
    if (g1) { s[0] = y0; s[1] = y1; } else { s[2] = y0; s[3] = y1; }
}

#define HC_BUF_BYTES (4 * 196 * 4)

__global__ void __launch_bounds__(NTHR, 1) __cluster_dims__(4, 1, 1)
lstm_cluster_kernel(
    const float* __restrict__ x,
    const float* __restrict__ w_ih1,  // [512][1]
    const float* __restrict__ w_hh1,  // [512][128]
    const float* __restrict__ b_ih1,
    const float* __restrict__ b_hh1,
    const float* __restrict__ w_ih2,  // [256][128]
    const float* __restrict__ w_hh2,  // [256][64]
    const float* __restrict__ b_ih2,
    const float* __restrict__ b_hh2,
    float* __restrict__ out)          // [128][64]
{
    const int tid  = threadIdx.x;
    const int lane = tid & 31;
    const int wrp  = tid >> 5;        // 8 warps
    const int q    = blockIdx.x & 3;
    const int cid  = blockIdx.x >> 2;

    // ---- L1 roles: lane = g(2b) | ks1(2b)<<2 | dlb<<4 ; rows (g,dl), (g,dl+16) ----
    const int g    = lane & 3;
    const int ks1  = (lane >> 2) & 3;
    const int dlb  = (lane >> 4) & 1;
    const int dl   = wrp * 2 + dlb;   // 0..15 ; rows dl and dl+16
    // ---- L2 roles: lane = g(2b) | ks2(3b)<<2 ; rows (g,dlp), (g,dlp+8) ----
    const int ks2  = lane >> 2;       // 0..7
    const int dlp  = wrp;             // 0..7 ; rows dlp and dlp+8

    // ---------------- weights -> registers (striped, 2 rows/thread) ----------------
    ulonglong2 w1a[8], w1b[8];
    {
        const int r0 = g * 128 + 32 * q + dl;
        const int r1 = r0 + 16;
        const float* wr0 = w_hh1 + r0 * 128 + ks1 * 4;
        const float* wr1 = w_hh1 + r1 * 128 + ks1 * 4;
#pragma unroll
        for (int kk = 0; kk < 8; kk++) {
            float4 f0 = *reinterpret_cast<const float4*>(wr0 + kk * 16);
            float4 f1 = *reinterpret_cast<const float4*>(wr1 + kk * 16);
            w1a[kk].x = pk(f0.x, f0.y); w1a[kk].y = pk(f0.z, f0.w);
            w1b[kk].x = pk(f1.x, f1.y); w1b[kk].y = pk(f1.z, f1.w);
        }
    }
    ulonglong2 w2a[6], w2b[6];
    {
        const int r0 = g * 64 + 16 * q + dlp;
        const int r1 = r0 + 8;
#pragma unroll
        for (int kk = 0; kk < 6; kk++) {
            int k0 = ks2 * 4 + kk * 32;
            float f0[4], f1[4];
#pragma unroll
            for (int e = 0; e < 4; e++) {
                int k = k0 + e;
                f0[e] = (k < 128) ? w_ih2[r0 * 128 + k] : w_hh2[r0 * 64 + (k - 128)];
                f1[e] = (k < 128) ? w_ih2[r1 * 128 + k] : w_hh2[r1 * 64 + (k - 128)];
            }
            w2a[kk].x = pk(f0[0], f0[1]); w2a[kk].y = pk(f0[2], f0[3]);
            w2b[kk].x = pk(f1[0], f1[1]); w2b[kk].y = pk(f1[2], f1[3]);
        }
    }

    // per-lane cell constants: 2 rows x 4 gates each
    float wih1c[2][4], b1c[2][4], b2c[2][4];
#pragma unroll
    for (int j = 0; j < 4; j++) {
        int ra = j * 128 + 32 * q + dl;
        int rb = ra + 16;
        wih1c[0][j] = w_ih1[ra];
        wih1c[1][j] = w_ih1[rb];
        b1c[0][j]   = b_ih1[ra] + b_hh1[ra];
        b1c[1][j]   = b_ih1[rb] + b_hh1[rb];
        int sa = j * 64 + 16 * q + dlp;
        int sb = sa + 8;
        b2c[0][j]   = b_ih2[sa] + b_hh2[sa];
        b2c[1][j]   = b_ih2[sb] + b_hh2[sb];
    }

    // ---------------- init smem ----------------
    for (int idx = tid; idx < 4 * 1024; idx += NTHR) {
        int b = idx >> 10, t = idx & 1023;
        sm.xs[t][b] = x[(4 * cid + b) * 1024 + t];
    }
    for (int idx = tid; idx < 3 * 4 * 196; idx += NTHR)
        (&sm.hc[0][0][0])[idx] = 0.0f;
    if (tid == 0) {
#pragma unroll
        for (int j = 0; j < 3; j++) {
            uint32_t a = s2u(&sm.mb[j]);
            asm volatile("mbarrier.init.shared.b64 [%0], 4;" :: "r"(a) : "memory");
        }
    }

    // ---------------- cluster address constants ----------------
    const uint32_t base0 = s2u(&sm);
    const uint32_t m0    = mapa_r(base0, 0);
    uint32_t dd[4];
    dd[0] = 0;
    dd[1] = mapa_r(base0, 1) - m0;
    dd[2] = mapa_r(base0, 2) - m0;
    dd[3] = mapa_r(base0, 3) - m0;
    const uint32_t HCO = s2u(&sm.hc[0][0][0]) - base0;
    const uint32_t MBO = s2u(&sm.mb[0]) - base0;
    const uint32_t rk1 = m0 + dd[ks1];        // L1 replica dst rank = ks1
    const uint32_t rk2 = m0 + dd[ks2 & 3];    // L2 replica dst rank = ks2&3

    csync();  // mbars + zeroed smem visible cluster-wide

    float c1a = 0.0f, c1b = 0.0f, c2a = 0.0f, c2b = 0.0f;
    const unsigned FULL = 0xffffffffu;

    for (int i = 0; i <= Tlen; i++) {
        const int bufW = i % 3;
        int bufR = 2;                 // zeroed buffer for i==0
        if (i >= 1) {
            const int im1 = i - 1;
            bufR = im1 % 3;
            mwait(base0 + MBO + bufR * 8, (uint32_t)((im1 / 3) & 1));
        }

        // ======== L1 (step i): shared-h dual-row dot ========
        if (i < Tlen) {
            float s0[4], s1[4];
#pragma unroll
            for (int b = 0; b < 4; b++) {
                const ulonglong2* hp =
                    reinterpret_cast<const ulonglong2*>(&sm.hc[bufR][b][0]);
                ull a00 = 0ull, a01 = 0ull, a10 = 0ull, a11 = 0ull;
#pragma unroll
                for (int kk = 0; kk < 8; kk++) {
                    ulonglong2 h = hp[ks1 + 4 * kk];
                    ffma2(a00, h.x, w1a[kk].x);
                    ffma2(a01, h.y, w1a[kk].y);
                    ffma2(a10, h.x, w1b[kk].x);
                    ffma2(a11, h.y, w1b[kk].y);
                }
                float2 f0 = u2f2(a00), f1 = u2f2(a01);
                float2 f2 = u2f2(a10), f3 = u2f2(a11);
                s0[b] = (f0.x + f0.y) + (f1.x + f1.y);
                s1[b] = (f2.x + f2.y) + (f3.x + f3.y);
            }
#pragma unroll
            for (int b = 0; b < 4; b++) {
                s0[b] += __shfl_xor_sync(FULL, s0[b], 4);
                s0[b] += __shfl_xor_sync(FULL, s0[b], 8);
                s1[b] += __shfl_xor_sync(FULL, s1[b], 4);
                s1[b] += __shfl_xor_sync(FULL, s1[b], 8);
            }
            transpose4(s0, g);
            transpose4(s1, g);
            const int beta = g;
            float xv = sm.xs[i][beta];
            // row a (dim dl)
            {
                float ai = fmaf(xv, wih1c[0][0], s0[0] + b1c[0][0]);
                float af = fmaf(xv, wih1c[0][1], s0[1] + b1c[0][1]);
                float ag = fmaf(xv, wih1c[0][2], s0[2] + b1c[0][2]);
                float ao = fmaf(xv, wih1c[0][3], s0[3] + b1c[0][3]);
                c1a = sigm(af) * c1a + sigm(ai) * tanha(ag);
                float h = sigm(ao) * tanha(c1a);
                st_cl(rk1 + HCO + bufW * HC_BUF_BYTES + (beta * 196 + 32 * q + dl) * 4, h);
            }
            // row b (dim dl+16)
            {
                float ai = fmaf(xv, wih1c[1][0], s1[0] + b1c[1][0]);
                float af = fmaf(xv, wih1c[1][1], s1[1] + b1c[1][1]);
                float ag = fmaf(xv, wih1c[1][2], s1[2] + b1c[1][2]);
                float ao = fmaf(xv, wih1c[1][3], s1[3] + b1c[1][3]);
                c1b = sigm(af) * c1b + sigm(ai) * tanha(ag);
                float h = sigm(ao) * tanha(c1b);
                st_cl(rk1 + HCO + bufW * HC_BUF_BYTES + (beta * 196 + 32 * q + dl + 16) * 4, h);
            }
        }

        // ======== L2 (step i-1): shared-h dual-row dot ========
        {
            float h2a = 0.0f, h2b = 0.0f;
            if (i >= 1) {
                float s0[4], s1[4];
#pragma unroll
                for (int b = 0; b < 4; b++) {
                    const ulonglong2* hp =
                        reinterpret_cast<const ulonglong2*>(&sm.hc[bufR][b][0]);
                    ull a00 = 0ull, a01 = 0ull, a10 = 0ull, a11 = 0ull;
#pragma unroll
                    for (int kk = 0; kk < 6; kk++) {
                        ulonglong2 h = hp[ks2 + 8 * kk];
                        ffma2(a00, h.x, w2a[kk].x);
                        ffma2(a01, h.y, w2a[kk].y);
                        ffma2(a10, h.x, w2b[kk].x);
                        ffma2(a11, h.y, w2b[kk].y);
                    }
                    float2 f0 = u2f2(a00), f1 = u2f2(a01);
                    float2 f2 = u2f2(a10), f3 = u2f2(a11);
                    s0[b] = (f0.x + f0.y) + (f1.x + f1.y);
                    s1[b] = (f2.x + f2.y) + (f3.x + f3.y);
                }
#pragma unroll
                for (int b = 0; b < 4; b++) {
                    s0[b] += __shfl_xor_sync(FULL, s0[b], 4);
                    s0[b] += __shfl_xor_sync(FULL, s0[b], 8);
                    s0[b] += __shfl_xor_sync(FULL, s0[b], 16);
                    s1[b] += __shfl_xor_sync(FULL, s1[b], 4);
                    s1[b] += __shfl_xor_sync(FULL, s1[b], 8);
                    s1[b] += __shfl_xor_sync(FULL, s1[b], 16);
                }
                transpose4(s0, g);
                transpose4(s1, g);
                {
                    float ai = s0[0] + b2c[0][0];
                    float af = s0[1] + b2c[0][1];
                    float ag = s0[2] + b2c[0][2];
                    float ao = s0[3] + b2c[0][3];
                    c2a = sigm(af) * c2a + sigm(ai) * tanha(ag);
                    h2a = sigm(ao) * tanha(c2a);
                }
                {
                    float ai = s1[0] + b2c[1][0];
                    float af = s1[1] + b2c[1][1];
                    float ag = s1[2] + b2c[1][2];
                    float ao = s1[3] + b2c[1][3];
                    c2b = sigm(af) * c2b + sigm(ai) * tanha(c2b * 0.0f + ag);
                    h2b = sigm(ao) * tanha(c2b);
                }
            }
            const int beta = g;
            if (i == Tlen) {
                if (ks2 == 0) out[(4 * cid + beta) * 64 + 16 * q + dlp] = h2a;
                if (ks2 == 1) out[(4 * cid + beta) * 64 + 16 * q + dlp + 8] = h2b;
            } else {
                // 8 ks lanes: lane ks2 stores row (ks2>=4 ? b : a) to rank ks2&3
                float hv = (ks2 >= 4) ? h2b : h2a;
                int   dv = (ks2 >= 4) ? (dlp + 8) : dlp;
                st_cl(rk2 + HCO + bufW * HC_BUF_BYTES + (beta * 196 + 128 + 16 * q + dv) * 4,
                      hv);
            }
        }

        // ======== publish step i's buffer ========
        if (i < Tlen) {
            __syncthreads();
            if (tid == 0) {
                fence_cluster();
                uint32_t am = m0 + MBO + bufW * 8;
                marr(am); marr(am + dd[1]); marr(am + dd[2]); marr(am + dd[3]);
            }
        }
    }

    csync();  // keep smem alive for peers
}

extern "C" void kernel_launch(void* const* d_in, const int* in_sizes, int n_in,
                              void* d_out, int out_size) {
    const float* x     = (const float*)d_in[0];
    const float* w_ih1 = (const float*)d_in[1];
    const float* w_hh1 = (const float*)d_in[2];
    const float* b_ih1 = (const float*)d_in[3];
    const float* b_hh1 = (const float*)d_in[4];
    const float* w_ih2 = (const float*)d_in[5];
    const float* w_hh2 = (const float*)d_in[6];
    const float* b_ih2 = (const float*)d_in[7];
    const float* b_hh2 = (const float*)d_in[8];
    float* out = (float*)d_out;

    lstm_cluster_kernel<<<NCTA, NTHR>>>(
        x, w_ih1, w_hh1, b_ih1, b_hh1, w_ih2, w_hh2, b_ih2, b_hh2, out);
    (void)in_sizes; (void)n_in; (void)out_size;
}